// round 5
// baseline (speedup 1.0000x reference)
#include <cuda_runtime.h>

// ---------------- problem constants ----------------
#define NP     13500
#define GRID   100
#define NG     (GRID*GRID*GRID)
#define NSUB   600
#define SUBPF  30

#define NBLK   141          // blocks (<= SM count -> co-resident, sw barrier safe)
#define NTHR   384          // 96 particles x 4 sub-threads
#define CHUNK  96           // particles per block (141*96 = 13536 >= NP)
#define NTOT   (NBLK*NTHR)

#define DT       5e-4f
#define DXS      0.01f
#define INV_DX   100.0f
#define MUC      38461.538461538461f     // E/(2(1+nu))
#define LAMC     57692.307692307695f     // E*nu/((1+nu)(1-2nu))
#define PMASS    3.7500000000000007e-4f  // p_vol * 3000
#define SCOEF    (-2.5e-6f)              // -DT*P_VOL*4*INV_DX^2
#define GRAVY    (-9.8f)
#define BOUNDC   3

// ---------------- persistent device state ----------------
__device__ float4   g_grid[3][NG];       // triple-buffered (vx,vy,vz,m)
__device__ int      g_bbox[6] = {0x7fffffff, 0x7fffffff, 0x7fffffff,
                                 (-0x7fffffff - 1), (-0x7fffffff - 1), (-0x7fffffff - 1)};
__device__ unsigned g_barcnt;            // monotone ticket barrier counter

// ---------------- software grid barrier ----------------
__device__ __forceinline__ void grid_barrier() {
    __syncthreads();
    if (threadIdx.x == 0) {
        __threadfence();
        unsigned t = atomicAdd(&g_barcnt, 1u);
        unsigned target = (t / NBLK + 1u) * NBLK;
        while (*((volatile unsigned*)&g_barcnt) < target) { }
        __threadfence();
    }
    __syncthreads();
}

__device__ __forceinline__ void bspline(float fx, float* w) {
    w[0] = 0.5f * (1.5f - fx) * (1.5f - fx);
    w[1] = 0.75f - (fx - 1.0f) * (fx - 1.0f);
    w[2] = 0.5f * (fx - 0.5f) * (fx - 0.5f);
}

__device__ __forceinline__ void red_add_v4(float4* p, float a, float b, float c, float d) {
    asm volatile(
        "{\n\t"
        ".reg .u64 ga;\n\t"
        "cvta.to.global.u64 ga, %0;\n\t"
        "red.global.add.v4.f32 [ga], {%1, %2, %3, %4};\n\t"
        "}"
        :: "l"(p), "f"(a), "f"(b), "f"(c), "f"(d) : "memory");
}

// F-update + neo-Hookean stress -> affine matrix (done redundantly by all 4 lanes)
__device__ __forceinline__ void fupdate_affine(const float* C, float* F, float* aff) {
    float A[9];
#pragma unroll
    for (int i = 0; i < 9; i++) A[i] = DT * C[i];
    A[0] += 1.0f; A[4] += 1.0f; A[8] += 1.0f;
    float Fn[9];
#pragma unroll
    for (int r = 0; r < 3; r++)
#pragma unroll
        for (int c = 0; c < 3; c++)
            Fn[r * 3 + c] = A[r * 3 + 0] * F[0 * 3 + c]
                          + A[r * 3 + 1] * F[1 * 3 + c]
                          + A[r * 3 + 2] * F[2 * 3 + c];
#pragma unroll
    for (int i = 0; i < 9; i++) F[i] = Fn[i];

    float c00 =  (F[4]*F[8] - F[5]*F[7]);
    float c01 = -(F[3]*F[8] - F[5]*F[6]);
    float c02 =  (F[3]*F[7] - F[4]*F[6]);
    float c10 = -(F[1]*F[8] - F[2]*F[7]);
    float c11 =  (F[0]*F[8] - F[2]*F[6]);
    float c12 = -(F[0]*F[7] - F[1]*F[6]);
    float c20 =  (F[1]*F[5] - F[2]*F[4]);
    float c21 = -(F[0]*F[5] - F[2]*F[3]);
    float c22 =  (F[0]*F[4] - F[1]*F[3]);
    float J = F[0]*c00 + F[1]*c01 + F[2]*c02;
    float invJ = 1.0f / J;
    float logJ = logf(fmaxf(J, 1e-6f));
    float Ft[9] = { c00*invJ, c01*invJ, c02*invJ,
                    c10*invJ, c11*invJ, c12*invJ,
                    c20*invJ, c21*invJ, c22*invJ };

    float Pm[9];
#pragma unroll
    for (int i = 0; i < 9; i++) Pm[i] = MUC * (F[i] - Ft[i]) + LAMC * logJ * Ft[i];
#pragma unroll
    for (int r = 0; r < 3; r++)
#pragma unroll
        for (int c = 0; c < 3; c++)
            aff[r * 3 + c] = SCOEF * (Pm[r*3+0]*F[c*3+0] + Pm[r*3+1]*F[c*3+1] + Pm[r*3+2]*F[c*3+2])
                           + PMASS * C[r * 3 + c];
}

// scatter this lane's subset of the 27-cell stencil
__device__ __forceinline__ void scatter_sub(
    int sub, float x0, float x1, float x2,
    float v0, float v1, float v2,
    const float* aff, float4* gw)
{
    int bx = (int)floorf(x0 * INV_DX - 0.5f);
    int by = (int)floorf(x1 * INV_DX - 0.5f);
    int bz = (int)floorf(x2 * INV_DX - 0.5f);
    float fx0 = x0 * INV_DX - (float)bx;
    float fx1 = x1 * INV_DX - (float)by;
    float fx2 = x2 * INV_DX - (float)bz;

    float wx[3], wy[3], wz[3];
    bspline(fx0, wx); bspline(fx1, wy); bspline(fx2, wz);

    float mv0 = PMASS * v0;
    float mv1 = PMASS * (v1 + DT * GRAVY);
    float mv2 = PMASS * v2;

#pragma unroll
    for (int cc = 0; cc < 7; cc++) {
        int c = cc * 4 + sub;
        if (c < 27) {
            int i = c / 9, j = (c % 9) / 3, k = c % 3;
            float d0 = ((float)i - fx0) * DXS;
            float d1 = ((float)j - fx1) * DXS;
            float d2 = ((float)k - fx2) * DXS;
            float wt = wx[i] * wy[j] * wz[k];
            int n0 = min(max(bx + i, 0), GRID - 1);
            int n1 = min(max(by + j, 0), GRID - 1);
            int n2 = min(max(bz + k, 0), GRID - 1);
            red_add_v4(&gw[(n0 * GRID + n1) * GRID + n2],
                       wt * (mv0 + aff[0]*d0 + aff[1]*d1 + aff[2]*d2),
                       wt * (mv1 + aff[3]*d0 + aff[4]*d1 + aff[5]*d2),
                       wt * (mv2 + aff[6]*d0 + aff[7]*d1 + aff[8]*d2),
                       wt * PMASS);
        }
    }
}

// ---------------- the whole simulation in one launch ----------------
__global__ void __launch_bounds__(NTHR, 1)
sim_kernel(const float* __restrict__ vptr,
           const float* __restrict__ q,
           const float* __restrict__ qd,
           float* __restrict__ out)
{
    const int t   = threadIdx.x;
    const int blk = blockIdx.x;
    const int tid = blk * NTHR + t;
    const int pi  = t >> 2;             // particle slot within block
    const int sub = t & 3;              // sub-thread within 4-lane group
    const int p   = blk * CHUNK + pi;
    const bool own = (p < NP);
    const float vs = vptr[0];

    __shared__ int sbb[6];

    // -------- persistent per-particle register state (replicated in 4 lanes) --------
    float x0 = 0.5f, x1 = 0.5f, x2 = 0.5f, v0 = 0.f, v1 = 0.f, v2 = 0.f;
    float C[9] = {0,0,0,0,0,0,0,0,0};
    float F[9] = {1,0,0,0,1,0,0,0,1};

    if (own) {
        x0 = q[p*3+0]; x1 = q[p*3+1]; x2 = q[p*3+2];
        v0 = qd[p*3+0]; v1 = qd[p*3+1]; v2 = qd[p*3+2];
    }

    // ================= Phase I: zero buffers + publish initial bbox =================
    if (t == 0) {
        sbb[0] = sbb[1] = sbb[2] = 0x7fffffff;
        sbb[3] = sbb[4] = sbb[5] = -0x7fffffff;
    }
    __syncthreads();
    {
        float4 z = make_float4(0.f, 0.f, 0.f, 0.f);
        for (int i = tid; i < NG; i += NTOT) {
            g_grid[0][i] = z; g_grid[1][i] = z; g_grid[2][i] = z;
        }
    }
    if (own && sub == 0) {
        int bx = (int)floorf(x0 * INV_DX - 0.5f);
        int by = (int)floorf(x1 * INV_DX - 0.5f);
        int bz = (int)floorf(x2 * INV_DX - 0.5f);
        atomicMin(&sbb[0], bx); atomicMax(&sbb[3], bx);
        atomicMin(&sbb[1], by); atomicMax(&sbb[4], by);
        atomicMin(&sbb[2], bz); atomicMax(&sbb[5], bz);
    }
    __syncthreads();
    if (t < 3) { atomicMin(&g_bbox[t], sbb[t]); atomicMax(&g_bbox[t + 3], sbb[t + 3]); }
    grid_barrier();

    // ================= Phase II: P2G(0) -> buf0 =================
    {
        float aff[9];
        fupdate_affine(C, F, aff);
        if (own) scatter_sub(sub, x0, x1, x2, v0, v1, v2, aff, g_grid[0]);
    }
    grid_barrier();

    // ================= fused substep loop =================
    for (int s = 0; s < NSUB - 1; s++) {
        const int rb = s % 3, wb = (s + 1) % 3, zb = (s + 2) % 3;
        const float4* gr = g_grid[rb];

        // frame dump (grid of substep s complete in buf[rb])
        if (s % SUBPF == SUBPF - 1) {
            float* of = out + (s / SUBPF) * NG;
            for (int i = tid; i < NG; i += NTOT) of[i] = __ldcg(&gr[i]).w + vs;
        }

        if (t == 0) {
            sbb[0] = sbb[1] = sbb[2] = 0x7fffffff;
            sbb[3] = sbb[4] = sbb[5] = -0x7fffffff;
        }
        __syncthreads();

        // ---- G2P gather (split across 4 lanes) ----
        {
            int bx = (int)floorf(x0 * INV_DX - 0.5f);
            int by = (int)floorf(x1 * INV_DX - 0.5f);
            int bz = (int)floorf(x2 * INV_DX - 0.5f);
            float fx0 = x0 * INV_DX - (float)bx;
            float fx1 = x1 * INV_DX - (float)by;
            float fx2 = x2 * INV_DX - (float)bz;

            float wx[3], wy[3], wz[3];
            bspline(fx0, wx); bspline(fx1, wy); bspline(fx2, wz);

            float r[12];   // nv0,nv1,nv2, Cm[0..8]
#pragma unroll
            for (int i = 0; i < 12; i++) r[i] = 0.f;

#pragma unroll
            for (int cc = 0; cc < 7; cc++) {
                int c = cc * 4 + sub;
                if (c < 27) {
                    int i = c / 9, j = (c % 9) / 3, k = c % 3;
                    int n0 = min(max(bx + i, 0), GRID - 1);
                    int n1 = min(max(by + j, 0), GRID - 1);
                    int n2 = min(max(bz + k, 0), GRID - 1);
                    float4 cell = __ldcg(&gr[(n0 * GRID + n1) * GRID + n2]);
                    float inv = 1.0f / (cell.w + vs);
                    float gv0 = cell.x * inv;
                    float gv1 = cell.y * inv;
                    float gv2 = cell.z * inv;
                    if (n0 < BOUNDC && gv0 < 0.f) gv0 = 0.f;
                    if (n0 >= GRID - BOUNDC && gv0 > 0.f) gv0 = 0.f;
                    if (n1 < BOUNDC && gv1 < 0.f) gv1 = 0.f;
                    if (n1 >= GRID - BOUNDC && gv1 > 0.f) gv1 = 0.f;
                    if (n2 < BOUNDC && gv2 < 0.f) gv2 = 0.f;
                    if (n2 >= GRID - BOUNDC && gv2 > 0.f) gv2 = 0.f;

                    float d0 = ((float)i - fx0) * DXS;
                    float d1 = ((float)j - fx1) * DXS;
                    float d2 = ((float)k - fx2) * DXS;
                    float wt = wx[i] * wy[j] * wz[k];

                    r[0] += wt * gv0; r[1] += wt * gv1; r[2] += wt * gv2;
                    r[3] += wt * gv0 * d0; r[4]  += wt * gv0 * d1; r[5]  += wt * gv0 * d2;
                    r[6] += wt * gv1 * d0; r[7]  += wt * gv1 * d1; r[8]  += wt * gv1 * d2;
                    r[9] += wt * gv2 * d0; r[10] += wt * gv2 * d1; r[11] += wt * gv2 * d2;
                }
            }

            // reduce across the 4-lane group (all lanes end with the total)
#pragma unroll
            for (int m = 1; m < 4; m <<= 1) {
#pragma unroll
                for (int i = 0; i < 12; i++)
                    r[i] += __shfl_xor_sync(0xffffffffu, r[i], m);
            }

            const float cscale = 4.0f * INV_DX * INV_DX;
#pragma unroll
            for (int i = 0; i < 9; i++) C[i] = cscale * r[3 + i];
            v0 = r[0]; v1 = r[1]; v2 = r[2];
            x0 += DT * v0; x1 += DT * v1; x2 += DT * v2;
        }

        // bbox of new base cells
        if (own && sub == 0) {
            int nbx = (int)floorf(x0 * INV_DX - 0.5f);
            int nby = (int)floorf(x1 * INV_DX - 0.5f);
            int nbz = (int)floorf(x2 * INV_DX - 0.5f);
            atomicMin(&sbb[0], nbx); atomicMax(&sbb[3], nbx);
            atomicMin(&sbb[1], nby); atomicMax(&sbb[4], nby);
            atomicMin(&sbb[2], nbz); atomicMax(&sbb[5], nbz);
        }

        // ---- P2G(s+1) scatter ----
        {
            float aff[9];
            fupdate_affine(C, F, aff);
            if (own) scatter_sub(sub, x0, x1, x2, v0, v1, v2, aff, g_grid[wb]);
        }

        // ---- zero buf[zb] over (monotone) bbox region ----
        {
            int x0c = max(g_bbox[0] - 2, 0), x1c = min(g_bbox[3] + 4, GRID - 1);
            int y0c = max(g_bbox[1] - 2, 0), y1c = min(g_bbox[4] + 4, GRID - 1);
            int z0c = max(g_bbox[2] - 2, 0), z1c = min(g_bbox[5] + 4, GRID - 1);
            int sx = x1c - x0c + 1, sy = y1c - y0c + 1, sz = z1c - z0c + 1;
            int vol = sx * sy * sz;
            float4* gz = g_grid[zb];
            float4 zf = make_float4(0.f, 0.f, 0.f, 0.f);
            for (int it = tid; it < vol; it += NTOT) {
                int iz = it % sz;
                int rem = it / sz;
                int iy = rem % sy;
                int ix = rem / sy;
                gz[((x0c + ix) * GRID + (y0c + iy)) * GRID + (z0c + iz)] = zf;
            }
        }

        __syncthreads();
        if (t < 3) { atomicMin(&g_bbox[t], sbb[t]); atomicMax(&g_bbox[t + 3], sbb[t + 3]); }
        grid_barrier();
    }

    // ================= final frame dump =================
    {
        const float4* gr = g_grid[(NSUB - 1) % 3];
        float* of = out + (NSUB / SUBPF - 1) * NG;
        for (int i = tid; i < NG; i += NTOT) of[i] = __ldcg(&gr[i]).w + vs;
    }
}

// ---------------- launch: ONE graph node ----------------
extern "C" void kernel_launch(void* const* d_in, const int* in_sizes, int n_in,
                              void* d_out, int out_size) {
    const float* v  = (const float*)d_in[0];
    const float* q  = (const float*)d_in[1];
    const float* qd = (const float*)d_in[2];
    float* out = (float*)d_out;

    sim_kernel<<<NBLK, NTHR>>>(v, q, qd, out);
}

// round 6
// speedup vs baseline: 1.0150x; 1.0150x over previous
#include <cuda_runtime.h>

// ---------------- problem constants ----------------
#define NP     13500
#define GRID   100
#define NG     (GRID*GRID*GRID)
#define NSUB   600
#define SUBPF  30

#define NBLK   141          // blocks (<= SM count -> co-resident, sw barrier safe)
#define NTHR   384          // 96 particles x 4 sub-threads
#define CHUNK  96           // particles per block (141*96 = 13536 >= NP)
#define NTOT   (NBLK*NTHR)

#define DT       5e-4f
#define DXS      0.01f
#define INV_DX   100.0f
#define MUC      38461.538461538461f     // E/(2(1+nu))
#define LAMC     57692.307692307695f     // E*nu/((1+nu)(1-2nu))
#define PMASS    3.7500000000000007e-4f  // p_vol * 3000
#define SCOEF    (-2.5e-6f)              // -DT*P_VOL*4*INV_DX^2
#define GRAVY    (-9.8f)
#define BOUNDC   3

// ---------------- persistent device state ----------------
__device__ float4   g_grid[3][NG];       // triple-buffered (vx,vy,vz,m)
__device__ int      g_bbox[6] = {0x7fffffff, 0x7fffffff, 0x7fffffff,
                                 (-0x7fffffff - 1), (-0x7fffffff - 1), (-0x7fffffff - 1)};
__device__ unsigned g_barcnt;            // monotone ticket barrier counter

// ---------------- software grid barrier ----------------
__device__ __forceinline__ void grid_barrier() {
    __syncthreads();
    if (threadIdx.x == 0) {
        __threadfence();
        unsigned t = atomicAdd(&g_barcnt, 1u);
        unsigned target = (t / NBLK + 1u) * NBLK;
        while (*((volatile unsigned*)&g_barcnt) < target) { }
        __threadfence();
    }
    __syncthreads();
}

__device__ __forceinline__ void bspline(float fx, float* w) {
    w[0] = 0.5f * (1.5f - fx) * (1.5f - fx);
    w[1] = 0.75f - (fx - 1.0f) * (fx - 1.0f);
    w[2] = 0.5f * (fx - 0.5f) * (fx - 0.5f);
}

__device__ __forceinline__ void red_add_v4(float4* p, float a, float b, float c, float d) {
    asm volatile(
        "{\n\t"
        ".reg .u64 ga;\n\t"
        "cvta.to.global.u64 ga, %0;\n\t"
        "red.global.add.v4.f32 [ga], {%1, %2, %3, %4};\n\t"
        "}"
        :: "l"(p), "f"(a), "f"(b), "f"(c), "f"(d) : "memory");
}

// F-update + neo-Hookean stress -> affine matrix (done redundantly by all 4 lanes)
__device__ __forceinline__ void fupdate_affine(const float* C, float* F, float* aff) {
    float A[9];
#pragma unroll
    for (int i = 0; i < 9; i++) A[i] = DT * C[i];
    A[0] += 1.0f; A[4] += 1.0f; A[8] += 1.0f;
    float Fn[9];
#pragma unroll
    for (int r = 0; r < 3; r++)
#pragma unroll
        for (int c = 0; c < 3; c++)
            Fn[r * 3 + c] = A[r * 3 + 0] * F[0 * 3 + c]
                          + A[r * 3 + 1] * F[1 * 3 + c]
                          + A[r * 3 + 2] * F[2 * 3 + c];
#pragma unroll
    for (int i = 0; i < 9; i++) F[i] = Fn[i];

    float c00 =  (F[4]*F[8] - F[5]*F[7]);
    float c01 = -(F[3]*F[8] - F[5]*F[6]);
    float c02 =  (F[3]*F[7] - F[4]*F[6]);
    float c10 = -(F[1]*F[8] - F[2]*F[7]);
    float c11 =  (F[0]*F[8] - F[2]*F[6]);
    float c12 = -(F[0]*F[7] - F[1]*F[6]);
    float c20 =  (F[1]*F[5] - F[2]*F[4]);
    float c21 = -(F[0]*F[5] - F[2]*F[3]);
    float c22 =  (F[0]*F[4] - F[1]*F[3]);
    float J = F[0]*c00 + F[1]*c01 + F[2]*c02;
    float invJ = 1.0f / J;
    float logJ = logf(fmaxf(J, 1e-6f));
    float Ft[9] = { c00*invJ, c01*invJ, c02*invJ,
                    c10*invJ, c11*invJ, c12*invJ,
                    c20*invJ, c21*invJ, c22*invJ };

    float Pm[9];
#pragma unroll
    for (int i = 0; i < 9; i++) Pm[i] = MUC * (F[i] - Ft[i]) + LAMC * logJ * Ft[i];
#pragma unroll
    for (int r = 0; r < 3; r++)
#pragma unroll
        for (int c = 0; c < 3; c++)
            aff[r * 3 + c] = SCOEF * (Pm[r*3+0]*F[c*3+0] + Pm[r*3+1]*F[c*3+1] + Pm[r*3+2]*F[c*3+2])
                           + PMASS * C[r * 3 + c];
}

// scatter this lane's subset of the 27-cell stencil
__device__ __forceinline__ void scatter_sub(
    int sub, float x0, float x1, float x2,
    float v0, float v1, float v2,
    const float* aff, float4* gw)
{
    int bx = (int)floorf(x0 * INV_DX - 0.5f);
    int by = (int)floorf(x1 * INV_DX - 0.5f);
    int bz = (int)floorf(x2 * INV_DX - 0.5f);
    float fx0 = x0 * INV_DX - (float)bx;
    float fx1 = x1 * INV_DX - (float)by;
    float fx2 = x2 * INV_DX - (float)bz;

    float wx[3], wy[3], wz[3];
    bspline(fx0, wx); bspline(fx1, wy); bspline(fx2, wz);

    float mv0 = PMASS * v0;
    float mv1 = PMASS * (v1 + DT * GRAVY);
    float mv2 = PMASS * v2;

#pragma unroll
    for (int cc = 0; cc < 7; cc++) {
        int c = cc * 4 + sub;
        if (c < 27) {
            int i = c / 9, j = (c % 9) / 3, k = c % 3;
            float d0 = ((float)i - fx0) * DXS;
            float d1 = ((float)j - fx1) * DXS;
            float d2 = ((float)k - fx2) * DXS;
            float wt = wx[i] * wy[j] * wz[k];
            int n0 = min(max(bx + i, 0), GRID - 1);
            int n1 = min(max(by + j, 0), GRID - 1);
            int n2 = min(max(bz + k, 0), GRID - 1);
            red_add_v4(&gw[(n0 * GRID + n1) * GRID + n2],
                       wt * (mv0 + aff[0]*d0 + aff[1]*d1 + aff[2]*d2),
                       wt * (mv1 + aff[3]*d0 + aff[4]*d1 + aff[5]*d2),
                       wt * (mv2 + aff[6]*d0 + aff[7]*d1 + aff[8]*d2),
                       wt * PMASS);
        }
    }
}

// ---------------- the whole simulation in one launch ----------------
__global__ void __launch_bounds__(NTHR, 1)
sim_kernel(const float* __restrict__ vptr,
           const float* __restrict__ q,
           const float* __restrict__ qd,
           float* __restrict__ out)
{
    const int t   = threadIdx.x;
    const int blk = blockIdx.x;
    const int tid = blk * NTHR + t;
    const int pi  = t >> 2;             // particle slot within block
    const int sub = t & 3;              // sub-thread within 4-lane group
    const int p   = blk * CHUNK + pi;
    const bool own = (p < NP);
    const float vs = vptr[0];

    __shared__ int sbb[6];

    // -------- persistent per-particle register state (replicated in 4 lanes) --------
    float x0 = 0.5f, x1 = 0.5f, x2 = 0.5f, v0 = 0.f, v1 = 0.f, v2 = 0.f;
    float C[9] = {0,0,0,0,0,0,0,0,0};
    float F[9] = {1,0,0,0,1,0,0,0,1};

    if (own) {
        x0 = q[p*3+0]; x1 = q[p*3+1]; x2 = q[p*3+2];
        v0 = qd[p*3+0]; v1 = qd[p*3+1]; v2 = qd[p*3+2];
    }

    // ================= Phase I: zero buffers + publish initial bbox =================
    if (t == 0) {
        sbb[0] = sbb[1] = sbb[2] = 0x7fffffff;
        sbb[3] = sbb[4] = sbb[5] = -0x7fffffff;
    }
    __syncthreads();
    {
        float4 z = make_float4(0.f, 0.f, 0.f, 0.f);
        for (int i = tid; i < NG; i += NTOT) {
            g_grid[0][i] = z; g_grid[1][i] = z; g_grid[2][i] = z;
        }
    }
    if (own && sub == 0) {
        int bx = (int)floorf(x0 * INV_DX - 0.5f);
        int by = (int)floorf(x1 * INV_DX - 0.5f);
        int bz = (int)floorf(x2 * INV_DX - 0.5f);
        atomicMin(&sbb[0], bx); atomicMax(&sbb[3], bx);
        atomicMin(&sbb[1], by); atomicMax(&sbb[4], by);
        atomicMin(&sbb[2], bz); atomicMax(&sbb[5], bz);
    }
    __syncthreads();
    if (t < 3) { atomicMin(&g_bbox[t], sbb[t]); atomicMax(&g_bbox[t + 3], sbb[t + 3]); }
    grid_barrier();

    // ================= Phase II: P2G(0) -> buf0 =================
    {
        float aff[9];
        fupdate_affine(C, F, aff);
        if (own) scatter_sub(sub, x0, x1, x2, v0, v1, v2, aff, g_grid[0]);
    }
    grid_barrier();

    // ================= fused substep loop =================
    for (int s = 0; s < NSUB - 1; s++) {
        const int rb = s % 3, wb = (s + 1) % 3, zb = (s + 2) % 3;
        const float4* gr = g_grid[rb];

        // frame dump (grid of substep s complete in buf[rb])
        if (s % SUBPF == SUBPF - 1) {
            float* of = out + (s / SUBPF) * NG;
            for (int i = tid; i < NG; i += NTOT) of[i] = __ldcg(&gr[i]).w + vs;
        }

        if (t == 0) {
            sbb[0] = sbb[1] = sbb[2] = 0x7fffffff;
            sbb[3] = sbb[4] = sbb[5] = -0x7fffffff;
        }
        __syncthreads();

        // ---- G2P gather (split across 4 lanes) ----
        {
            int bx = (int)floorf(x0 * INV_DX - 0.5f);
            int by = (int)floorf(x1 * INV_DX - 0.5f);
            int bz = (int)floorf(x2 * INV_DX - 0.5f);
            float fx0 = x0 * INV_DX - (float)bx;
            float fx1 = x1 * INV_DX - (float)by;
            float fx2 = x2 * INV_DX - (float)bz;

            float wx[3], wy[3], wz[3];
            bspline(fx0, wx); bspline(fx1, wy); bspline(fx2, wz);

            float r[12];   // nv0,nv1,nv2, Cm[0..8]
#pragma unroll
            for (int i = 0; i < 12; i++) r[i] = 0.f;

#pragma unroll
            for (int cc = 0; cc < 7; cc++) {
                int c = cc * 4 + sub;
                if (c < 27) {
                    int i = c / 9, j = (c % 9) / 3, k = c % 3;
                    int n0 = min(max(bx + i, 0), GRID - 1);
                    int n1 = min(max(by + j, 0), GRID - 1);
                    int n2 = min(max(bz + k, 0), GRID - 1);
                    float4 cell = __ldcg(&gr[(n0 * GRID + n1) * GRID + n2]);
                    float inv = 1.0f / (cell.w + vs);
                    float gv0 = cell.x * inv;
                    float gv1 = cell.y * inv;
                    float gv2 = cell.z * inv;
                    if (n0 < BOUNDC && gv0 < 0.f) gv0 = 0.f;
                    if (n0 >= GRID - BOUNDC && gv0 > 0.f) gv0 = 0.f;
                    if (n1 < BOUNDC && gv1 < 0.f) gv1 = 0.f;
                    if (n1 >= GRID - BOUNDC && gv1 > 0.f) gv1 = 0.f;
                    if (n2 < BOUNDC && gv2 < 0.f) gv2 = 0.f;
                    if (n2 >= GRID - BOUNDC && gv2 > 0.f) gv2 = 0.f;

                    float d0 = ((float)i - fx0) * DXS;
                    float d1 = ((float)j - fx1) * DXS;
                    float d2 = ((float)k - fx2) * DXS;
                    float wt = wx[i] * wy[j] * wz[k];

                    r[0] += wt * gv0; r[1] += wt * gv1; r[2] += wt * gv2;
                    r[3] += wt * gv0 * d0; r[4]  += wt * gv0 * d1; r[5]  += wt * gv0 * d2;
                    r[6] += wt * gv1 * d0; r[7]  += wt * gv1 * d1; r[8]  += wt * gv1 * d2;
                    r[9] += wt * gv2 * d0; r[10] += wt * gv2 * d1; r[11] += wt * gv2 * d2;
                }
            }

            // reduce across the 4-lane group (all lanes end with the total)
#pragma unroll
            for (int m = 1; m < 4; m <<= 1) {
#pragma unroll
                for (int i = 0; i < 12; i++)
                    r[i] += __shfl_xor_sync(0xffffffffu, r[i], m);
            }

            const float cscale = 4.0f * INV_DX * INV_DX;
#pragma unroll
            for (int i = 0; i < 9; i++) C[i] = cscale * r[3 + i];
            v0 = r[0]; v1 = r[1]; v2 = r[2];
            x0 += DT * v0; x1 += DT * v1; x2 += DT * v2;
        }

        // bbox of new base cells
        if (own && sub == 0) {
            int nbx = (int)floorf(x0 * INV_DX - 0.5f);
            int nby = (int)floorf(x1 * INV_DX - 0.5f);
            int nbz = (int)floorf(x2 * INV_DX - 0.5f);
            atomicMin(&sbb[0], nbx); atomicMax(&sbb[3], nbx);
            atomicMin(&sbb[1], nby); atomicMax(&sbb[4], nby);
            atomicMin(&sbb[2], nbz); atomicMax(&sbb[5], nbz);
        }

        // ---- P2G(s+1) scatter ----
        {
            float aff[9];
            fupdate_affine(C, F, aff);
            if (own) scatter_sub(sub, x0, x1, x2, v0, v1, v2, aff, g_grid[wb]);
        }

        // ---- zero buf[zb] over (monotone) bbox region ----
        {
            int x0c = max(g_bbox[0] - 2, 0), x1c = min(g_bbox[3] + 4, GRID - 1);
            int y0c = max(g_bbox[1] - 2, 0), y1c = min(g_bbox[4] + 4, GRID - 1);
            int z0c = max(g_bbox[2] - 2, 0), z1c = min(g_bbox[5] + 4, GRID - 1);
            int sx = x1c - x0c + 1, sy = y1c - y0c + 1, sz = z1c - z0c + 1;
            int vol = sx * sy * sz;
            float4* gz = g_grid[zb];
            float4 zf = make_float4(0.f, 0.f, 0.f, 0.f);
            for (int it = tid; it < vol; it += NTOT) {
                int iz = it % sz;
                int rem = it / sz;
                int iy = rem % sy;
                int ix = rem / sy;
                gz[((x0c + ix) * GRID + (y0c + iy)) * GRID + (z0c + iz)] = zf;
            }
        }

        __syncthreads();
        if (t < 3) { atomicMin(&g_bbox[t], sbb[t]); atomicMax(&g_bbox[t + 3], sbb[t + 3]); }
        grid_barrier();
    }

    // ================= final frame dump =================
    {
        const float4* gr = g_grid[(NSUB - 1) % 3];
        float* of = out + (NSUB / SUBPF - 1) * NG;
        for (int i = tid; i < NG; i += NTOT) of[i] = __ldcg(&gr[i]).w + vs;
    }
}

// ---------------- launch: ONE graph node ----------------
extern "C" void kernel_launch(void* const* d_in, const int* in_sizes, int n_in,
                              void* d_out, int out_size) {
    const float* v  = (const float*)d_in[0];
    const float* q  = (const float*)d_in[1];
    const float* qd = (const float*)d_in[2];
    float* out = (float*)d_out;

    sim_kernel<<<NBLK, NTHR>>>(v, q, qd, out);
}

// round 8
// speedup vs baseline: 1.1702x; 1.1529x over previous
#include <cuda_runtime.h>

// ---------------- problem constants ----------------
#define NP     13500
#define GRID   100
#define NG     (GRID*GRID*GRID)
#define NSUB   600
#define SUBPF  30

#define NBLK   141          // blocks (<= SM count -> co-resident, sw barrier safe)
#define NTHR   384          // 96 particles x 4 sub-threads
#define CHUNK  96           // particles per block (141*96 = 13536 >= NP)
#define NTOT   (NBLK*NTHR)

#define DT       5e-4f
#define DXS      0.01f
#define INV_DX   100.0f
#define MUC      38461.538461538461f     // E/(2(1+nu))
#define LAMC     57692.307692307695f     // E*nu/((1+nu)(1-2nu))
#define PMASS    3.7500000000000007e-4f  // p_vol * 3000
#define SCOEF    (-2.5e-6f)              // -DT*P_VOL*4*INV_DX^2
#define GRAVY    (-9.8f)
#define BOUNDC   3

// ---------------- persistent device state ----------------
__device__ float4   g_grid[3][NG];       // triple-buffered (vx,vy,vz,m)
__device__ int      g_bbox[6] = {0x7fffffff, 0x7fffffff, 0x7fffffff,
                                 (-0x7fffffff - 1), (-0x7fffffff - 1), (-0x7fffffff - 1)};
__device__ unsigned g_barcnt;            // monotone ticket barrier counter

// ---------------- software grid barrier ----------------
__device__ __forceinline__ void grid_barrier() {
    __syncthreads();
    if (threadIdx.x == 0) {
        __threadfence();
        unsigned t = atomicAdd(&g_barcnt, 1u);
        unsigned target = (t / NBLK + 1u) * NBLK;
        while (*((volatile unsigned*)&g_barcnt) < target) { }
        __threadfence();
    }
    __syncthreads();
}

__device__ __forceinline__ void bspline(float fx, float* w) {
    w[0] = 0.5f * (1.5f - fx) * (1.5f - fx);
    w[1] = 0.75f - (fx - 1.0f) * (fx - 1.0f);
    w[2] = 0.5f * (fx - 0.5f) * (fx - 0.5f);
}

__device__ __forceinline__ void red_add_v4(float4* p, float a, float b, float c, float d) {
    asm volatile(
        "{\n\t"
        ".reg .u64 ga;\n\t"
        "cvta.to.global.u64 ga, %0;\n\t"
        "red.global.add.v4.f32 [ga], {%1, %2, %3, %4};\n\t"
        "}"
        :: "l"(p), "f"(a), "f"(b), "f"(c), "f"(d) : "memory");
}

// F-update + neo-Hookean stress -> affine matrix (done redundantly by all 4 lanes)
__device__ __forceinline__ void fupdate_affine(const float* C, float* F, float* aff) {
    float A[9];
#pragma unroll
    for (int i = 0; i < 9; i++) A[i] = DT * C[i];
    A[0] += 1.0f; A[4] += 1.0f; A[8] += 1.0f;
    float Fn[9];
#pragma unroll
    for (int r = 0; r < 3; r++)
#pragma unroll
        for (int c = 0; c < 3; c++)
            Fn[r * 3 + c] = A[r * 3 + 0] * F[0 * 3 + c]
                          + A[r * 3 + 1] * F[1 * 3 + c]
                          + A[r * 3 + 2] * F[2 * 3 + c];
#pragma unroll
    for (int i = 0; i < 9; i++) F[i] = Fn[i];

    float c00 =  (F[4]*F[8] - F[5]*F[7]);
    float c01 = -(F[3]*F[8] - F[5]*F[6]);
    float c02 =  (F[3]*F[7] - F[4]*F[6]);
    float c10 = -(F[1]*F[8] - F[2]*F[7]);
    float c11 =  (F[0]*F[8] - F[2]*F[6]);
    float c12 = -(F[0]*F[7] - F[1]*F[6]);
    float c20 =  (F[1]*F[5] - F[2]*F[4]);
    float c21 = -(F[0]*F[5] - F[2]*F[3]);
    float c22 =  (F[0]*F[4] - F[1]*F[3]);
    float J = F[0]*c00 + F[1]*c01 + F[2]*c02;
    float invJ = 1.0f / J;
    float logJ = logf(fmaxf(J, 1e-6f));
    float Ft[9] = { c00*invJ, c01*invJ, c02*invJ,
                    c10*invJ, c11*invJ, c12*invJ,
                    c20*invJ, c21*invJ, c22*invJ };

    float Pm[9];
#pragma unroll
    for (int i = 0; i < 9; i++) Pm[i] = MUC * (F[i] - Ft[i]) + LAMC * logJ * Ft[i];
#pragma unroll
    for (int r = 0; r < 3; r++)
#pragma unroll
        for (int c = 0; c < 3; c++)
            aff[r * 3 + c] = SCOEF * (Pm[r*3+0]*F[c*3+0] + Pm[r*3+1]*F[c*3+1] + Pm[r*3+2]*F[c*3+2])
                           + PMASS * C[r * 3 + c];
}

// scatter this lane's subset of the 27-cell stencil, with warp-level
// dedup: butterfly over xor-distances 4/8/16 merges lanes (same stencil
// offset, neighboring particles) that target the identical grid cell.
__device__ __forceinline__ void scatter_sub(
    int sub, bool own, float x0, float x1, float x2,
    float v0, float v1, float v2,
    const float* aff, float4* gw)
{
    int bx = (int)floorf(x0 * INV_DX - 0.5f);
    int by = (int)floorf(x1 * INV_DX - 0.5f);
    int bz = (int)floorf(x2 * INV_DX - 0.5f);
    float fx0 = x0 * INV_DX - (float)bx;
    float fx1 = x1 * INV_DX - (float)by;
    float fx2 = x2 * INV_DX - (float)bz;

    float wx[3], wy[3], wz[3];
    bspline(fx0, wx); bspline(fx1, wy); bspline(fx2, wz);

    float mv0 = PMASS * v0;
    float mv1 = PMASS * (v1 + DT * GRAVY);
    float mv2 = PMASS * v2;

#pragma unroll
    for (int cc = 0; cc < 7; cc++) {
        int c = cc * 4 + sub;
        bool alive = own && (c < 27);
        int idx = -1;
        float s0 = 0.f, s1 = 0.f, s2 = 0.f, s3 = 0.f;
        if (alive) {
            int i = c / 9, j = (c % 9) / 3, k = c % 3;
            float d0 = ((float)i - fx0) * DXS;
            float d1 = ((float)j - fx1) * DXS;
            float d2 = ((float)k - fx2) * DXS;
            float wt = wx[i] * wy[j] * wz[k];
            int n0 = min(max(bx + i, 0), GRID - 1);
            int n1 = min(max(by + j, 0), GRID - 1);
            int n2 = min(max(bz + k, 0), GRID - 1);
            idx = (n0 * GRID + n1) * GRID + n2;
            s0 = wt * (mv0 + aff[0]*d0 + aff[1]*d1 + aff[2]*d2);
            s1 = wt * (mv1 + aff[3]*d0 + aff[4]*d1 + aff[5]*d2);
            s2 = wt * (mv2 + aff[6]*d0 + aff[7]*d1 + aff[8]*d2);
            s3 = wt * PMASS;
        }

        // butterfly merge across neighboring particles in the warp
#pragma unroll
        for (int d = 4; d <= 16; d <<= 1) {
            int      oidx = __shfl_xor_sync(0xffffffffu, idx, d);
            float    o0   = __shfl_xor_sync(0xffffffffu, s0, d);
            float    o1   = __shfl_xor_sync(0xffffffffu, s1, d);
            float    o2   = __shfl_xor_sync(0xffffffffu, s2, d);
            float    o3   = __shfl_xor_sync(0xffffffffu, s3, d);
            unsigned oal  = __shfl_xor_sync(0xffffffffu, (unsigned)alive, d);
            bool match = alive && oal && (oidx == idx);
            if (match) {
                if ((threadIdx.x & d) == 0) { s0 += o0; s1 += o1; s2 += o2; s3 += o3; }
                else alive = false;
            }
        }

        if (alive) red_add_v4(&gw[idx], s0, s1, s2, s3);
    }
}

// ---------------- the whole simulation in one launch ----------------
__global__ void __launch_bounds__(NTHR, 1)
sim_kernel(const float* __restrict__ vptr,
           const float* __restrict__ q,
           const float* __restrict__ qd,
           float* __restrict__ out)
{
    const int t   = threadIdx.x;
    const int blk = blockIdx.x;
    const int tid = blk * NTHR + t;
    const int pi  = t >> 2;             // particle slot within block
    const int sub = t & 3;              // sub-thread within 4-lane group
    const int p   = blk * CHUNK + pi;
    const bool own = (p < NP);
    const float vs = vptr[0];

    __shared__ int sbb[6];

    // -------- persistent per-particle register state (replicated in 4 lanes) --------
    float x0 = 0.5f, x1 = 0.5f, x2 = 0.5f, v0 = 0.f, v1 = 0.f, v2 = 0.f;
    float C[9] = {0,0,0,0,0,0,0,0,0};
    float F[9] = {1,0,0,0,1,0,0,0,1};

    if (own) {
        x0 = q[p*3+0]; x1 = q[p*3+1]; x2 = q[p*3+2];
        v0 = qd[p*3+0]; v1 = qd[p*3+1]; v2 = qd[p*3+2];
    }

    // ================= Phase I: zero buffers + publish initial bbox =================
    if (t == 0) {
        sbb[0] = sbb[1] = sbb[2] = 0x7fffffff;
        sbb[3] = sbb[4] = sbb[5] = -0x7fffffff;
    }
    __syncthreads();
    {
        float4 z = make_float4(0.f, 0.f, 0.f, 0.f);
        for (int i = tid; i < NG; i += NTOT) {
            g_grid[0][i] = z; g_grid[1][i] = z; g_grid[2][i] = z;
        }
    }
    if (own && sub == 0) {
        int bx = (int)floorf(x0 * INV_DX - 0.5f);
        int by = (int)floorf(x1 * INV_DX - 0.5f);
        int bz = (int)floorf(x2 * INV_DX - 0.5f);
        atomicMin(&sbb[0], bx); atomicMax(&sbb[3], bx);
        atomicMin(&sbb[1], by); atomicMax(&sbb[4], by);
        atomicMin(&sbb[2], bz); atomicMax(&sbb[5], bz);
    }
    __syncthreads();
    if (t < 3) { atomicMin(&g_bbox[t], sbb[t]); atomicMax(&g_bbox[t + 3], sbb[t + 3]); }
    grid_barrier();

    // ================= Phase II: P2G(0) -> buf0 =================
    {
        float aff[9];
        fupdate_affine(C, F, aff);
        scatter_sub(sub, own, x0, x1, x2, v0, v1, v2, aff, g_grid[0]);
    }
    grid_barrier();

    // ================= fused substep loop =================
    for (int s = 0; s < NSUB - 1; s++) {
        const int rb = s % 3, wb = (s + 1) % 3, zb = (s + 2) % 3;
        const float4* gr = g_grid[rb];

        // frame dump (grid of substep s complete in buf[rb])
        if (s % SUBPF == SUBPF - 1) {
            float* of = out + (s / SUBPF) * NG;
            for (int i = tid; i < NG; i += NTOT) of[i] = __ldcg(&gr[i]).w + vs;
        }

        if (t == 0) {
            sbb[0] = sbb[1] = sbb[2] = 0x7fffffff;
            sbb[3] = sbb[4] = sbb[5] = -0x7fffffff;
        }
        __syncthreads();

        // ---- G2P gather (split across 4 lanes) ----
        {
            int bx = (int)floorf(x0 * INV_DX - 0.5f);
            int by = (int)floorf(x1 * INV_DX - 0.5f);
            int bz = (int)floorf(x2 * INV_DX - 0.5f);
            float fx0 = x0 * INV_DX - (float)bx;
            float fx1 = x1 * INV_DX - (float)by;
            float fx2 = x2 * INV_DX - (float)bz;

            float wx[3], wy[3], wz[3];
            bspline(fx0, wx); bspline(fx1, wy); bspline(fx2, wz);

            float r[12];   // nv0,nv1,nv2, Cm[0..8]
#pragma unroll
            for (int i = 0; i < 12; i++) r[i] = 0.f;

#pragma unroll
            for (int cc = 0; cc < 7; cc++) {
                int c = cc * 4 + sub;
                if (c < 27) {
                    int i = c / 9, j = (c % 9) / 3, k = c % 3;
                    int n0 = min(max(bx + i, 0), GRID - 1);
                    int n1 = min(max(by + j, 0), GRID - 1);
                    int n2 = min(max(bz + k, 0), GRID - 1);
                    float4 cell = __ldcg(&gr[(n0 * GRID + n1) * GRID + n2]);
                    float inv = 1.0f / (cell.w + vs);
                    float gv0 = cell.x * inv;
                    float gv1 = cell.y * inv;
                    float gv2 = cell.z * inv;
                    if (n0 < BOUNDC && gv0 < 0.f) gv0 = 0.f;
                    if (n0 >= GRID - BOUNDC && gv0 > 0.f) gv0 = 0.f;
                    if (n1 < BOUNDC && gv1 < 0.f) gv1 = 0.f;
                    if (n1 >= GRID - BOUNDC && gv1 > 0.f) gv1 = 0.f;
                    if (n2 < BOUNDC && gv2 < 0.f) gv2 = 0.f;
                    if (n2 >= GRID - BOUNDC && gv2 > 0.f) gv2 = 0.f;

                    float d0 = ((float)i - fx0) * DXS;
                    float d1 = ((float)j - fx1) * DXS;
                    float d2 = ((float)k - fx2) * DXS;
                    float wt = wx[i] * wy[j] * wz[k];

                    r[0] += wt * gv0; r[1] += wt * gv1; r[2] += wt * gv2;
                    r[3] += wt * gv0 * d0; r[4]  += wt * gv0 * d1; r[5]  += wt * gv0 * d2;
                    r[6] += wt * gv1 * d0; r[7]  += wt * gv1 * d1; r[8]  += wt * gv1 * d2;
                    r[9] += wt * gv2 * d0; r[10] += wt * gv2 * d1; r[11] += wt * gv2 * d2;
                }
            }

            // reduce across the 4-lane group (all lanes end with the total)
#pragma unroll
            for (int m = 1; m < 4; m <<= 1) {
#pragma unroll
                for (int i = 0; i < 12; i++)
                    r[i] += __shfl_xor_sync(0xffffffffu, r[i], m);
            }

            const float cscale = 4.0f * INV_DX * INV_DX;
#pragma unroll
            for (int i = 0; i < 9; i++) C[i] = cscale * r[3 + i];
            v0 = r[0]; v1 = r[1]; v2 = r[2];
            x0 += DT * v0; x1 += DT * v1; x2 += DT * v2;
        }

        // bbox of new base cells
        if (own && sub == 0) {
            int nbx = (int)floorf(x0 * INV_DX - 0.5f);
            int nby = (int)floorf(x1 * INV_DX - 0.5f);
            int nbz = (int)floorf(x2 * INV_DX - 0.5f);
            atomicMin(&sbb[0], nbx); atomicMax(&sbb[3], nbx);
            atomicMin(&sbb[1], nby); atomicMax(&sbb[4], nby);
            atomicMin(&sbb[2], nbz); atomicMax(&sbb[5], nbz);
        }

        // ---- P2G(s+1) scatter (warp-deduplicated) ----
        {
            float aff[9];
            fupdate_affine(C, F, aff);
            scatter_sub(sub, own, x0, x1, x2, v0, v1, v2, aff, g_grid[wb]);
        }

        // ---- zero buf[zb] over (monotone) bbox region ----
        {
            int x0c = max(g_bbox[0] - 2, 0), x1c = min(g_bbox[3] + 4, GRID - 1);
            int y0c = max(g_bbox[1] - 2, 0), y1c = min(g_bbox[4] + 4, GRID - 1);
            int z0c = max(g_bbox[2] - 2, 0), z1c = min(g_bbox[5] + 4, GRID - 1);
            int sx = x1c - x0c + 1, sy = y1c - y0c + 1, sz = z1c - z0c + 1;
            int vol = sx * sy * sz;
            float4* gz = g_grid[zb];
            float4 zf = make_float4(0.f, 0.f, 0.f, 0.f);
            for (int it = tid; it < vol; it += NTOT) {
                int iz = it % sz;
                int rem = it / sz;
                int iy = rem % sy;
                int ix = rem / sy;
                gz[((x0c + ix) * GRID + (y0c + iy)) * GRID + (z0c + iz)] = zf;
            }
        }

        __syncthreads();
        if (t < 3) { atomicMin(&g_bbox[t], sbb[t]); atomicMax(&g_bbox[t + 3], sbb[t + 3]); }
        grid_barrier();
    }

    // ================= final frame dump =================
    {
        const float4* gr = g_grid[(NSUB - 1) % 3];
        float* of = out + (NSUB / SUBPF - 1) * NG;
        for (int i = tid; i < NG; i += NTOT) of[i] = __ldcg(&gr[i]).w + vs;
    }
}

// ---------------- launch: ONE graph node ----------------
extern "C" void kernel_launch(void* const* d_in, const int* in_sizes, int n_in,
                              void* d_out, int out_size) {
    const float* v  = (const float*)d_in[0];
    const float* q  = (const float*)d_in[1];
    const float* qd = (const float*)d_in[2];
    float* out = (float*)d_out;

    sim_kernel<<<NBLK, NTHR>>>(v, q, qd, out);
}